// round 6
// baseline (speedup 1.0000x reference)
#include <cuda_runtime.h>
#include <math.h>

#define T_ 48
#define B_ 16
#define H_ 16
#define W_ 48
#define D_ 684
#define N_ 256
#define M_ 256
#define A_ 512
#define CQ_ 512
#define HW_ 768
#define PH_ 26
#define PW_ 58

// ------------- device scratch (no dynamic allocation allowed) -------------
__device__ float g_RT[121 * A_];          // R^T: [k][a]
__device__ float g_Uctx[B_ * HW_ * A_];   // Ua_ctx + Ua_b + Uf_b, layout [b][pos][a]
__device__ float g_sz[T_ * B_ * N_];
__device__ float g_sr[T_ * B_ * N_];
__device__ float g_sh[T_ * B_ * N_];
__device__ float g_h[B_ * N_];
__device__ float g_h1[B_ * N_];
__device__ float g_ap[B_ * PH_ * PW_];    // zero-padded alpha_past
__device__ float g_ee[B_ * HW_];          // exp(e)*mask
__device__ float g_S[B_];                 // softmax denominators

__device__ __forceinline__ float sigm(float x) {
    return __fdividef(1.f, 1.f + __expf(-x));
}
__device__ __forceinline__ float tanh_acc(float x) {
    float z = __expf(2.f * x);
    return 1.f - __fdividef(2.f, z + 1.f);
}

// packed f32x2 helpers (FFMA2 path — ptxas never emits this from C++)
__device__ __forceinline__ unsigned long long pack2(float lo, float hi) {
    unsigned long long r;
    asm("mov.b64 %0, {%1, %2};" : "=l"(r) : "f"(lo), "f"(hi));
    return r;
}
__device__ __forceinline__ unsigned long long ffma2(unsigned long long a,
                                                    unsigned long long b,
                                                    unsigned long long c) {
    unsigned long long d;
    asm("fma.rn.f32x2 %0, %1, %2, %3;" : "=l"(d) : "l"(a), "l"(b), "l"(c));
    return d;
}
__device__ __forceinline__ void unpack2(unsigned long long v, float& lo, float& hi) {
    asm("mov.b64 {%0, %1}, %2;" : "=f"(lo), "=f"(hi) : "l"(v));
}

// ------------- precompute R^T[k][a] = sum_c Uf[a,c] * Q[c,k] -------------
__global__ void k_pre_R(const float* __restrict__ Uf_w, const float* __restrict__ Q_w) {
    __shared__ float Qs[CQ_];
    int k = blockIdx.x;  // 0..120
    for (int c = threadIdx.x; c < CQ_; c += 256) Qs[c] = Q_w[c * 121 + k];
    __syncthreads();
    for (int a = threadIdx.x; a < A_; a += 256) {
        const float* u = Uf_w + (size_t)a * CQ_;
        float s = 0.f;
        for (int c = 0; c < CQ_; c += 4) {
            float4 u4 = *(const float4*)(u + c);
            s += u4.x * Qs[c] + u4.y * Qs[c + 1] + u4.z * Qs[c + 2] + u4.w * Qs[c + 3];
        }
        g_RT[k * A_ + a] = s;
    }
}

// ------------- precompute sz/sr/sh = emb @ Wy*.T + b -------------
__global__ void k_pre_szrh(const float* __restrict__ emb,
                           const float* __restrict__ Wyz, const float* __restrict__ bz,
                           const float* __restrict__ Wyr, const float* __restrict__ br,
                           const float* __restrict__ Wyh, const float* __restrict__ bh) {
    __shared__ float es[M_];
    int tb = blockIdx.x;
    es[threadIdx.x] = emb[(size_t)tb * M_ + threadIdx.x];
    __syncthreads();
    int n = threadIdx.x;
    const float* wz = Wyz + (size_t)n * M_;
    const float* wr = Wyr + (size_t)n * M_;
    const float* wh = Wyh + (size_t)n * M_;
    float az = 0.f, ar = 0.f, ah = 0.f;
    for (int m = 0; m < M_; m += 4) {
        float4 z4 = *(const float4*)(wz + m);
        float4 r4 = *(const float4*)(wr + m);
        float4 h4 = *(const float4*)(wh + m);
        float e0 = es[m], e1 = es[m + 1], e2 = es[m + 2], e3 = es[m + 3];
        az += z4.x * e0 + z4.y * e1 + z4.z * e2 + z4.w * e3;
        ar += r4.x * e0 + r4.y * e1 + r4.z * e2 + r4.w * e3;
        ah += h4.x * e0 + h4.y * e1 + h4.z * e2 + h4.w * e3;
    }
    g_sz[tb * N_ + n] = az + bz[n];
    g_sr[tb * N_ + n] = ar + br[n];
    g_sh[tb * N_ + n] = ah + bh[n];
}

// ------------- precompute Uctx[b][pos][a] = ctx . Ua_w + Ua_b + Uf_b -------------
__global__ void k_uactx(const float* __restrict__ ctx, const float* __restrict__ Ua_w,
                        const float* __restrict__ Ua_b, const float* __restrict__ Uf_b) {
    __shared__ float As[16][64];   // [dd][pos]
    __shared__ float Bs[16][68];   // [dd][a], padded
    int b = blockIdx.z;
    int p0 = blockIdx.x * 64;
    int a0 = blockIdx.y * 64;
    int tid = threadIdx.x;
    int ty = tid >> 4, tx = tid & 15;
    float acc[4][4];
#pragma unroll
    for (int i = 0; i < 4; i++)
#pragma unroll
        for (int j = 0; j < 4; j++) acc[i][j] = 0.f;

    int dda = tid >> 4;
    int pp4 = (tid & 15) * 4;
    int aab = tid >> 2;
    int dd4 = (tid & 3) * 4;

    for (int d0 = 0; d0 < D_; d0 += 16) {
        float4 av = make_float4(0.f, 0.f, 0.f, 0.f);
        if (d0 + dda < D_)
            av = *(const float4*)(ctx + ((size_t)b * D_ + d0 + dda) * HW_ + p0 + pp4);
        *(float4*)&As[dda][pp4] = av;
        float4 bv = make_float4(0.f, 0.f, 0.f, 0.f);
        if (d0 + dd4 < D_)
            bv = *(const float4*)(Ua_w + (size_t)(a0 + aab) * D_ + d0 + dd4);
        Bs[dd4][aab] = bv.x;
        Bs[dd4 + 1][aab] = bv.y;
        Bs[dd4 + 2][aab] = bv.z;
        Bs[dd4 + 3][aab] = bv.w;
        __syncthreads();
#pragma unroll
        for (int dd = 0; dd < 16; ++dd) {
            float4 af = *(const float4*)&As[dd][ty * 4];
            float4 bf = *(const float4*)&Bs[dd][tx * 4];
            acc[0][0] += af.x * bf.x; acc[0][1] += af.x * bf.y; acc[0][2] += af.x * bf.z; acc[0][3] += af.x * bf.w;
            acc[1][0] += af.y * bf.x; acc[1][1] += af.y * bf.y; acc[1][2] += af.y * bf.z; acc[1][3] += af.y * bf.w;
            acc[2][0] += af.z * bf.x; acc[2][1] += af.z * bf.y; acc[2][2] += af.z * bf.z; acc[2][3] += af.z * bf.w;
            acc[3][0] += af.w * bf.x; acc[3][1] += af.w * bf.y; acc[3][2] += af.w * bf.z; acc[3][3] += af.w * bf.w;
        }
        __syncthreads();
    }
#pragma unroll
    for (int i = 0; i < 4; i++) {
        int pos = p0 + ty * 4 + i;
#pragma unroll
        for (int j = 0; j < 4; j++) {
            int a = a0 + tx * 4 + j;
            g_Uctx[((size_t)b * HW_ + pos) * A_ + a] = acc[i][j] + Ua_b[a] + Uf_b[a];
        }
    }
}

// ------------- init: zero ap + softmax denom, copy init state -------------
__global__ void k_init(const float* __restrict__ h0) {
    int i = blockIdx.x * blockDim.x + threadIdx.x;
    if (i < B_ * PH_ * PW_) g_ap[i] = 0.f;
    if (i < B_ * N_) g_h[i] = h0[i];
    if (i < B_) g_S[i] = 0.f;
}

// ------------- prologue only: GRU1 for t=0 -------------
__global__ void k_gru1(const float* __restrict__ Uhz, const float* __restrict__ Uhr,
                       const float* __restrict__ Uhh, const float* __restrict__ mask, int t) {
    __shared__ float hs[N_];
    int b = blockIdx.x, s = blockIdx.y, tid = threadIdx.x;
    for (int x = tid; x < N_; x += 64) hs[x] = g_h[b * N_ + x];
    __syncthreads();
    int n = s * 64 + tid;
    const float* wz = Uhz + (size_t)n * N_;
    const float* wr = Uhr + (size_t)n * N_;
    const float* wh = Uhh + (size_t)n * N_;
    float az = 0.f, ar = 0.f, ah = 0.f;
    for (int m = 0; m < N_; m += 4) {
        float4 z4 = *(const float4*)(wz + m);
        float4 r4 = *(const float4*)(wr + m);
        float4 h4 = *(const float4*)(wh + m);
        float e0 = hs[m], e1 = hs[m + 1], e2 = hs[m + 2], e3 = hs[m + 3];
        az += z4.x * e0 + z4.y * e1 + z4.z * e2 + z4.w * e3;
        ar += r4.x * e0 + r4.y * e1 + r4.z * e2 + r4.w * e3;
        ah += h4.x * e0 + h4.y * e1 + h4.z * e2 + h4.w * e3;
    }
    int tb = t * B_ + b;
    float z1 = sigm(az + g_sz[tb * N_ + n]);
    float r1 = sigm(ar + g_sr[tb * N_ + n]);
    float h1p = tanh_acc(ah * r1 + g_sh[tb * N_ + n]);
    float hv = hs[n];
    float h1 = z1 * hv + (1.f - z1) * h1p;
    float m = mask[tb];
    g_h1[b * N_ + n] = m * h1 + (1.f - m) * hv;
}

// ------------- per step: coverage-conv + attention energies (FFMA2 mainloop) ---
// grid (B, 8): each CTA = one batch, two output rows (96 positions).
// R staged in 4 chunks of 128 'a' channels. Energies warp-reduced, exp(e)*mask
// written to g_ee, denominators accumulated atomically into g_S.
#define CONV_SMEM_BYTES ((121 * 128 + 12 * PW_ + A_ + N_) * 4)
__global__ __launch_bounds__(256, 1) void k_conv(const float* __restrict__ Wa_w,
                                                 const float* __restrict__ va_w,
                                                 const float* __restrict__ va_b,
                                                 const float* __restrict__ cmask, int t) {
    extern __shared__ float sm[];
    float* Rs = sm;                      // [121][128]
    float* P = Rs + 121 * 128;           // [12][PW_]
    float* Wah = P + 12 * PW_;           // [512]
    float* h1s = Wah + A_;               // [256]
    int b = blockIdx.x, tile = blockIdx.y;
    int tid = threadIdx.x;
    h1s[tid] = g_h1[b * N_ + tid];
    int r0 = tile * 2;
    for (int x = tid; x < 12 * PW_; x += 256)
        P[x] = g_ap[(b * PH_ + r0 + x / PW_) * PW_ + x % PW_];
    __syncthreads();
    for (int a = tid; a < A_; a += 256) {     // Wa @ h1 (redundant per CTA, cheap)
        const float* wr = Wa_w + (size_t)a * N_;
        float s = 0.f;
        for (int n = 0; n < N_; n += 4) {
            float4 w4 = *(const float4*)(wr + n);
            s += w4.x * h1s[n] + w4.y * h1s[n + 1] + w4.z * h1s[n + 2] + w4.w * h1s[n + 3];
        }
        Wah[a] = s;
    }
    __syncthreads();

    int w = tid >> 5, l = tid & 31;
    int lr = w >> 2, c0 = (w & 3) * 12;      // warp -> row-in-tile, 12-col group
    const float* prowbase = P + lr * PW_ + c0;
    int posbase = tile * 96 + w * 12;
    float ep[12];
#pragma unroll
    for (int j = 0; j < 12; j++) ep[j] = 0.f;

    for (int chunk = 0; chunk < 4; ++chunk) {
        for (int x = tid; x < 121 * 128; x += 256)
            Rs[x] = g_RT[(x >> 7) * A_ + chunk * 128 + (x & 127)];
        __syncthreads();
        // packed accumulators: acc2[i][jp] holds positions (2jp, 2jp+1) for
        // channel subgroup i (a = chunk*128 + i*32 + lane)
        unsigned long long acc2[4][6];
#pragma unroll
        for (int i = 0; i < 4; i++)
#pragma unroll
            for (int jp = 0; jp < 6; jp++) acc2[i][jp] = 0ull;
#pragma unroll
        for (int dy = 0; dy < 11; ++dy) {
            float pr[22];
#pragma unroll
            for (int q = 0; q < 22; ++q) pr[q] = prowbase[dy * PW_ + q];
            unsigned long long pp[21];
#pragma unroll
            for (int q = 0; q < 21; ++q) pp[q] = pack2(pr[q], pr[q + 1]);
            const float* rrow = Rs + dy * 11 * 128 + l;
#pragma unroll
            for (int dx = 0; dx < 11; ++dx) {
                float rv0 = rrow[dx * 128];
                float rv1 = rrow[dx * 128 + 32];
                float rv2 = rrow[dx * 128 + 64];
                float rv3 = rrow[dx * 128 + 96];
                unsigned long long rd0 = pack2(rv0, rv0);
                unsigned long long rd1 = pack2(rv1, rv1);
                unsigned long long rd2 = pack2(rv2, rv2);
                unsigned long long rd3 = pack2(rv3, rv3);
#pragma unroll
                for (int jp = 0; jp < 6; ++jp) {
                    unsigned long long pv = pp[dx + 2 * jp];
                    acc2[0][jp] = ffma2(rd0, pv, acc2[0][jp]);
                    acc2[1][jp] = ffma2(rd1, pv, acc2[1][jp]);
                    acc2[2][jp] = ffma2(rd2, pv, acc2[2][jp]);
                    acc2[3][jp] = ffma2(rd3, pv, acc2[3][jp]);
                }
            }
        }
#pragma unroll
        for (int i = 0; i < 4; ++i) {
            int a = chunk * 128 + i * 32 + l;
            float vav = va_w[a];
            float wahv = Wah[a];
            const float* up = g_Uctx + ((size_t)b * HW_ + posbase) * A_ + a;
#pragma unroll
            for (int jp = 0; jp < 6; ++jp) {
                float x0, x1;
                unpack2(acc2[i][jp], x0, x1);
                int j = 2 * jp;
                float xv0 = x0 + up[(size_t)j * A_] + wahv;
                ep[j] += vav * tanh_acc(xv0);
                float xv1 = x1 + up[(size_t)(j + 1) * A_] + wahv;
                ep[j + 1] += vav * tanh_acc(xv1);
            }
        }
        __syncthreads();
    }
#pragma unroll
    for (int j = 0; j < 12; ++j) {       // reduce the 32 lanes (128 'a' channels)
        float v = ep[j];
        v += __shfl_down_sync(0xffffffffu, v, 16);
        v += __shfl_down_sync(0xffffffffu, v, 8);
        v += __shfl_down_sync(0xffffffffu, v, 4);
        v += __shfl_down_sync(0xffffffffu, v, 2);
        v += __shfl_down_sync(0xffffffffu, v, 1);
        ep[j] = v;
    }
    if (l == 0) {
        float vb = va_b[0];
        float ssum = 0.f;
#pragma unroll
        for (int j = 0; j < 12; ++j) {
            int pos = posbase + j;
            float ee = __expf(ep[j] + vb) * cmask[b * HW_ + pos];
            g_ee[b * HW_ + pos] = ee;
            ssum += ee;
        }
        atomicAdd(&g_S[b], ssum);
    }
}

// ------------- per step: fused softmax + ap + ct + GRU2 + GRU1(t+1) -------------
// grid (B,), 256 threads. h2 handed to GRU1 through shared memory.
__global__ void k_fused(const float* __restrict__ ctx,
                        const float* __restrict__ Wcz, const float* __restrict__ Wcr,
                        const float* __restrict__ Wch,
                        const float* __restrict__ Uhz2, const float* __restrict__ bz2,
                        const float* __restrict__ Uhr2, const float* __restrict__ br2,
                        const float* __restrict__ Uhh2, const float* __restrict__ bh2,
                        const float* __restrict__ Uhz, const float* __restrict__ Uhr,
                        const float* __restrict__ Uhh,
                        const float* __restrict__ mask, int t,
                        float* __restrict__ o_al, float* __restrict__ o_ap,
                        float* __restrict__ o_ct, float* __restrict__ o_h2) {
    __shared__ float als[HW_];
    __shared__ float cts[D_];
    __shared__ float h1s[N_];
    __shared__ float h2s[N_];
    __shared__ float sinv;
    int b = blockIdx.x, tid = threadIdx.x;
    if (tid == 0) sinv = __fdividef(1.f, g_S[b]);
    h1s[tid] = g_h1[b * N_ + tid];
    __syncthreads();
    if (tid == 0) g_S[b] = 0.f;         // reset denom for next step's conv
    float inv = sinv;
    // softmax + alpha_past update + outputs
    for (int x = tid; x < HW_; x += 256) {
        float av = g_ee[b * HW_ + x] * inv;
        als[x] = av;
        o_al[(size_t)(t * B_ + b) * HW_ + x] = av;
        int r = x / W_, c = x - r * W_;
        int api = (b * PH_ + r + 5) * PW_ + c + 5;
        float apn = g_ap[api] + av;
        g_ap[api] = apn;
        o_ap[(size_t)(t * B_ + b) * HW_ + x] = apn;
    }
    __syncthreads();
    // context vector ct[b][d]
    for (int d = tid; d < D_; d += 256) {
        const float* crow = ctx + ((size_t)b * D_ + d) * HW_;
        float s0 = 0.f, s1 = 0.f, s2 = 0.f, s3 = 0.f;
        for (int x = 0; x < HW_; x += 4) {
            float4 c4 = *(const float4*)(crow + x);
            s0 += c4.x * als[x];
            s1 += c4.y * als[x + 1];
            s2 += c4.z * als[x + 2];
            s3 += c4.w * als[x + 3];
        }
        float ctv = (s0 + s1) + (s2 + s3);
        cts[d] = ctv;
        o_ct[(size_t)(t * B_ + b) * D_ + d] = ctv;
    }
    __syncthreads();
    // GRU2: n = tid
    {
        int n = tid;
        const float* wz = Wcz + (size_t)n * D_;
        const float* wr = Wcr + (size_t)n * D_;
        const float* wh = Wch + (size_t)n * D_;
        float cz = 0.f, cr = 0.f, ch = 0.f;
        for (int d = 0; d < D_; d += 4) {
            float4 z4 = *(const float4*)(wz + d);
            float4 r4 = *(const float4*)(wr + d);
            float4 h4 = *(const float4*)(wh + d);
            float c0 = cts[d], c1 = cts[d + 1], c2 = cts[d + 2], c3 = cts[d + 3];
            cz += z4.x * c0 + z4.y * c1 + z4.z * c2 + z4.w * c3;
            cr += r4.x * c0 + r4.y * c1 + r4.z * c2 + r4.w * c3;
            ch += h4.x * c0 + h4.y * c1 + h4.z * c2 + h4.w * c3;
        }
        const float* uz = Uhz2 + (size_t)n * N_;
        const float* ur = Uhr2 + (size_t)n * N_;
        const float* uh = Uhh2 + (size_t)n * N_;
        float az = 0.f, ar = 0.f, ah = 0.f;
        for (int m = 0; m < N_; m += 4) {
            float4 z4 = *(const float4*)(uz + m);
            float4 r4 = *(const float4*)(ur + m);
            float4 h4 = *(const float4*)(uh + m);
            float e0 = h1s[m], e1 = h1s[m + 1], e2 = h1s[m + 2], e3 = h1s[m + 3];
            az += z4.x * e0 + z4.y * e1 + z4.z * e2 + z4.w * e3;
            ar += r4.x * e0 + r4.y * e1 + r4.z * e2 + r4.w * e3;
            ah += h4.x * e0 + h4.y * e1 + h4.z * e2 + h4.w * e3;
        }
        float z2 = sigm(cz + az + bz2[n]);
        float r2 = sigm(cr + ar + br2[n]);
        float h2p = tanh_acc(ch + (ah + bh2[n]) * r2);
        float h1v = h1s[n];
        float h2 = z2 * h1v + (1.f - z2) * h2p;
        float m = mask[t * B_ + b];
        h2 = m * h2 + (1.f - m) * h1v;
        h2s[n] = h2;
        o_h2[(size_t)(t * B_ + b) * N_ + n] = h2;
    }
    __syncthreads();
    // GRU1 for step t+1 (consumes h2 from smem)
    if (t + 1 < T_) {
        int n = tid;
        const float* wz = Uhz + (size_t)n * N_;
        const float* wr = Uhr + (size_t)n * N_;
        const float* wh = Uhh + (size_t)n * N_;
        float az = 0.f, ar = 0.f, ah = 0.f;
        for (int m = 0; m < N_; m += 4) {
            float4 z4 = *(const float4*)(wz + m);
            float4 r4 = *(const float4*)(wr + m);
            float4 h4 = *(const float4*)(wh + m);
            float e0 = h2s[m], e1 = h2s[m + 1], e2 = h2s[m + 2], e3 = h2s[m + 3];
            az += z4.x * e0 + z4.y * e1 + z4.z * e2 + z4.w * e3;
            ar += r4.x * e0 + r4.y * e1 + r4.z * e2 + r4.w * e3;
            ah += h4.x * e0 + h4.y * e1 + h4.z * e2 + h4.w * e3;
        }
        int tb = (t + 1) * B_ + b;
        float z1 = sigm(az + g_sz[tb * N_ + n]);
        float r1 = sigm(ar + g_sr[tb * N_ + n]);
        float h1p = tanh_acc(ah * r1 + g_sh[tb * N_ + n]);
        float hv = h2s[n];
        float h1 = z1 * hv + (1.f - z1) * h1p;
        float m = mask[tb];
        g_h1[b * N_ + n] = m * h1 + (1.f - m) * hv;
    }
}

extern "C" void kernel_launch(void* const* d_in, const int* in_sizes, int n_in,
                              void* d_out, int out_size) {
    const float* emb   = (const float*)d_in[0];
    const float* mask  = (const float*)d_in[1];
    const float* ctx   = (const float*)d_in[2];
    const float* cmask = (const float*)d_in[3];
    const float* h0    = (const float*)d_in[4];
    const float* Ua_w  = (const float*)d_in[5];
    const float* Ua_b  = (const float*)d_in[6];
    const float* Wa_w  = (const float*)d_in[7];
    const float* Q_w   = (const float*)d_in[8];
    const float* Uf_w  = (const float*)d_in[9];
    const float* Uf_b  = (const float*)d_in[10];
    const float* va_w  = (const float*)d_in[11];
    const float* va_b  = (const float*)d_in[12];
    const float* Wyz_w = (const float*)d_in[13];
    const float* Wyz_b = (const float*)d_in[14];
    const float* Wyr_w = (const float*)d_in[15];
    const float* Wyr_b = (const float*)d_in[16];
    const float* Wyh_w = (const float*)d_in[17];
    const float* Wyh_b = (const float*)d_in[18];
    const float* Uhz_w = (const float*)d_in[19];
    const float* Uhr_w = (const float*)d_in[20];
    const float* Uhh_w = (const float*)d_in[21];
    const float* Wcz_w = (const float*)d_in[22];
    const float* Wcr_w = (const float*)d_in[23];
    const float* Wch_w = (const float*)d_in[24];
    const float* Uhz2_w = (const float*)d_in[25];
    const float* Uhz2_b = (const float*)d_in[26];
    const float* Uhr2_w = (const float*)d_in[27];
    const float* Uhr2_b = (const float*)d_in[28];
    const float* Uhh2_w = (const float*)d_in[29];
    const float* Uhh2_b = (const float*)d_in[30];

    float* out  = (float*)d_out;
    float* o_h2 = out;                                   // [T,B,N]
    float* o_ct = o_h2 + (size_t)T_ * B_ * N_;           // [T,B,D]
    float* o_al = o_ct + (size_t)T_ * B_ * D_;           // [T,B,H,W]
    float* o_ap = o_al + (size_t)T_ * B_ * HW_;          // [T,B,H,W]

    static int smem_set = 0;
    if (!smem_set) {
        cudaFuncSetAttribute(k_conv, cudaFuncAttributeMaxDynamicSharedMemorySize,
                             CONV_SMEM_BYTES);
        smem_set = 1;
    }

    // one-time precomputes
    k_pre_R<<<121, 256>>>(Uf_w, Q_w);
    k_pre_szrh<<<T_ * B_, 256>>>(emb, Wyz_w, Wyz_b, Wyr_w, Wyr_b, Wyh_w, Wyh_b);
    k_uactx<<<dim3(HW_ / 64, A_ / 64, B_), 256>>>(ctx, Ua_w, Ua_b, Uf_b);
    k_init<<<(B_ * PH_ * PW_ + 255) / 256, 256>>>(h0);
    k_gru1<<<dim3(B_, 4), 64>>>(Uhz_w, Uhr_w, Uhh_w, mask, 0);   // prologue h1(0)

    // 48 sequential steps, 2 launches each
    for (int t = 0; t < T_; ++t) {
        k_conv<<<dim3(B_, 8), 256, CONV_SMEM_BYTES>>>(Wa_w, va_w, va_b, cmask, t);
        k_fused<<<B_, 256>>>(ctx, Wcz_w, Wcr_w, Wch_w, Uhz2_w, Uhz2_b,
                             Uhr2_w, Uhr2_b, Uhh2_w, Uhh2_b,
                             Uhz_w, Uhr_w, Uhh_w, mask, t,
                             o_al, o_ap, o_ct, o_h2);
    }
    (void)in_sizes; (void)n_in; (void)out_size;
}

// round 8
// speedup vs baseline: 1.0023x; 1.0023x over previous
#include <cuda_runtime.h>
#include <math.h>

#define T_ 48
#define B_ 16
#define H_ 16
#define W_ 48
#define D_ 684
#define N_ 256
#define M_ 256
#define A_ 512
#define CQ_ 512
#define HW_ 768
#define PH_ 26
#define PW_ 58

// ------------- device scratch (no dynamic allocation allowed) -------------
__device__ float g_RT[121 * A_];          // R^T: [k][a]
__device__ float g_Uctx[B_ * HW_ * A_];   // Ua_ctx + Ua_b + Uf_b, layout [b][pos][a]
__device__ float g_sz[T_ * B_ * N_];
__device__ float g_sr[T_ * B_ * N_];
__device__ float g_sh[T_ * B_ * N_];
__device__ float g_h[B_ * N_];
__device__ float g_h1[B_ * N_];
__device__ float g_ap[B_ * PH_ * PW_];    // zero-padded alpha_past
__device__ float g_ee[B_ * HW_];          // exp(e)*mask
__device__ float g_S[B_];                 // softmax denominators

__device__ __forceinline__ float sigm(float x) {
    return __fdividef(1.f, 1.f + __expf(-x));
}
__device__ __forceinline__ float tanh_acc(float x) {
    float z = __expf(2.f * x);
    return 1.f - __fdividef(2.f, z + 1.f);
}

// ------------- precompute R^T[k][a] = sum_c Uf[a,c] * Q[c,k] -------------
__global__ void k_pre_R(const float* __restrict__ Uf_w, const float* __restrict__ Q_w) {
    __shared__ float Qs[CQ_];
    int k = blockIdx.x;  // 0..120
    for (int c = threadIdx.x; c < CQ_; c += 256) Qs[c] = Q_w[c * 121 + k];
    __syncthreads();
    for (int a = threadIdx.x; a < A_; a += 256) {
        const float* u = Uf_w + (size_t)a * CQ_;
        float s = 0.f;
        for (int c = 0; c < CQ_; c += 4) {
            float4 u4 = *(const float4*)(u + c);
            s += u4.x * Qs[c] + u4.y * Qs[c + 1] + u4.z * Qs[c + 2] + u4.w * Qs[c + 3];
        }
        g_RT[k * A_ + a] = s;
    }
}

// ------------- precompute sz/sr/sh = emb @ Wy*.T + b -------------
__global__ void k_pre_szrh(const float* __restrict__ emb,
                           const float* __restrict__ Wyz, const float* __restrict__ bz,
                           const float* __restrict__ Wyr, const float* __restrict__ br,
                           const float* __restrict__ Wyh, const float* __restrict__ bh) {
    __shared__ float es[M_];
    int tb = blockIdx.x;
    es[threadIdx.x] = emb[(size_t)tb * M_ + threadIdx.x];
    __syncthreads();
    int n = threadIdx.x;
    const float* wz = Wyz + (size_t)n * M_;
    const float* wr = Wyr + (size_t)n * M_;
    const float* wh = Wyh + (size_t)n * M_;
    float az = 0.f, ar = 0.f, ah = 0.f;
    for (int m = 0; m < M_; m += 4) {
        float4 z4 = *(const float4*)(wz + m);
        float4 r4 = *(const float4*)(wr + m);
        float4 h4 = *(const float4*)(wh + m);
        float e0 = es[m], e1 = es[m + 1], e2 = es[m + 2], e3 = es[m + 3];
        az += z4.x * e0 + z4.y * e1 + z4.z * e2 + z4.w * e3;
        ar += r4.x * e0 + r4.y * e1 + r4.z * e2 + r4.w * e3;
        ah += h4.x * e0 + h4.y * e1 + h4.z * e2 + h4.w * e3;
    }
    g_sz[tb * N_ + n] = az + bz[n];
    g_sr[tb * N_ + n] = ar + br[n];
    g_sh[tb * N_ + n] = ah + bh[n];
}

// ------------- precompute Uctx[b][pos][a] = ctx . Ua_w + Ua_b + Uf_b -------------
__global__ void k_uactx(const float* __restrict__ ctx, const float* __restrict__ Ua_w,
                        const float* __restrict__ Ua_b, const float* __restrict__ Uf_b) {
    __shared__ float As[16][64];   // [dd][pos]
    __shared__ float Bs[16][68];   // [dd][a], padded
    int b = blockIdx.z;
    int p0 = blockIdx.x * 64;
    int a0 = blockIdx.y * 64;
    int tid = threadIdx.x;
    int ty = tid >> 4, tx = tid & 15;
    float acc[4][4];
#pragma unroll
    for (int i = 0; i < 4; i++)
#pragma unroll
        for (int j = 0; j < 4; j++) acc[i][j] = 0.f;

    int dda = tid >> 4;
    int pp4 = (tid & 15) * 4;
    int aab = tid >> 2;
    int dd4 = (tid & 3) * 4;

    for (int d0 = 0; d0 < D_; d0 += 16) {
        float4 av = make_float4(0.f, 0.f, 0.f, 0.f);
        if (d0 + dda < D_)
            av = *(const float4*)(ctx + ((size_t)b * D_ + d0 + dda) * HW_ + p0 + pp4);
        *(float4*)&As[dda][pp4] = av;
        float4 bv = make_float4(0.f, 0.f, 0.f, 0.f);
        if (d0 + dd4 < D_)
            bv = *(const float4*)(Ua_w + (size_t)(a0 + aab) * D_ + d0 + dd4);
        Bs[dd4][aab] = bv.x;
        Bs[dd4 + 1][aab] = bv.y;
        Bs[dd4 + 2][aab] = bv.z;
        Bs[dd4 + 3][aab] = bv.w;
        __syncthreads();
#pragma unroll
        for (int dd = 0; dd < 16; ++dd) {
            float4 af = *(const float4*)&As[dd][ty * 4];
            float4 bf = *(const float4*)&Bs[dd][tx * 4];
            acc[0][0] += af.x * bf.x; acc[0][1] += af.x * bf.y; acc[0][2] += af.x * bf.z; acc[0][3] += af.x * bf.w;
            acc[1][0] += af.y * bf.x; acc[1][1] += af.y * bf.y; acc[1][2] += af.y * bf.z; acc[1][3] += af.y * bf.w;
            acc[2][0] += af.z * bf.x; acc[2][1] += af.z * bf.y; acc[2][2] += af.z * bf.z; acc[2][3] += af.z * bf.w;
            acc[3][0] += af.w * bf.x; acc[3][1] += af.w * bf.y; acc[3][2] += af.w * bf.z; acc[3][3] += af.w * bf.w;
        }
        __syncthreads();
    }
#pragma unroll
    for (int i = 0; i < 4; i++) {
        int pos = p0 + ty * 4 + i;
#pragma unroll
        for (int j = 0; j < 4; j++) {
            int a = a0 + tx * 4 + j;
            g_Uctx[((size_t)b * HW_ + pos) * A_ + a] = acc[i][j] + Ua_b[a] + Uf_b[a];
        }
    }
}

// ------------- init: zero ap + softmax denom, copy init state -------------
__global__ void k_init(const float* __restrict__ h0) {
    int i = blockIdx.x * blockDim.x + threadIdx.x;
    if (i < B_ * PH_ * PW_) g_ap[i] = 0.f;
    if (i < B_ * N_) g_h[i] = h0[i];
    if (i < B_) g_S[i] = 0.f;
}

// ------------- prologue only: GRU1 for t=0 -------------
__global__ void k_gru1(const float* __restrict__ Uhz, const float* __restrict__ Uhr,
                       const float* __restrict__ Uhh, const float* __restrict__ mask, int t) {
    __shared__ float hs[N_];
    int b = blockIdx.x, s = blockIdx.y, tid = threadIdx.x;
    for (int x = tid; x < N_; x += 64) hs[x] = g_h[b * N_ + x];
    __syncthreads();
    int n = s * 64 + tid;
    const float* wz = Uhz + (size_t)n * N_;
    const float* wr = Uhr + (size_t)n * N_;
    const float* wh = Uhh + (size_t)n * N_;
    float az = 0.f, ar = 0.f, ah = 0.f;
    for (int m = 0; m < N_; m += 4) {
        float4 z4 = *(const float4*)(wz + m);
        float4 r4 = *(const float4*)(wr + m);
        float4 h4 = *(const float4*)(wh + m);
        float e0 = hs[m], e1 = hs[m + 1], e2 = hs[m + 2], e3 = hs[m + 3];
        az += z4.x * e0 + z4.y * e1 + z4.z * e2 + z4.w * e3;
        ar += r4.x * e0 + r4.y * e1 + r4.z * e2 + r4.w * e3;
        ah += h4.x * e0 + h4.y * e1 + h4.z * e2 + h4.w * e3;
    }
    int tb = t * B_ + b;
    float z1 = sigm(az + g_sz[tb * N_ + n]);
    float r1 = sigm(ar + g_sr[tb * N_ + n]);
    float h1p = tanh_acc(ah * r1 + g_sh[tb * N_ + n]);
    float hv = hs[n];
    float h1 = z1 * hv + (1.f - z1) * h1p;
    float m = mask[tb];
    g_h1[b * N_ + n] = m * h1 + (1.f - m) * hv;
}

// ------------- per step: coverage-conv + attention energies (scalar FFMA) -----
// grid (B, 8): each CTA = one batch, two output rows (96 positions).
// R staged in 4 chunks of 128 'a' channels. Energies warp-reduced, exp(e)*mask
// written to g_ee, denominators accumulated atomically into g_S.
#define CONV_SMEM_BYTES ((121 * 128 + 12 * PW_ + A_ + N_) * 4)
__global__ __launch_bounds__(256, 1) void k_conv(const float* __restrict__ Wa_w,
                                                 const float* __restrict__ va_w,
                                                 const float* __restrict__ va_b,
                                                 const float* __restrict__ cmask, int t) {
    extern __shared__ float sm[];
    float* Rs = sm;                      // [121][128]
    float* P = Rs + 121 * 128;           // [12][PW_]
    float* Wah = P + 12 * PW_;           // [512]
    float* h1s = Wah + A_;               // [256]
    int b = blockIdx.x, tile = blockIdx.y;
    int tid = threadIdx.x;
    h1s[tid] = g_h1[b * N_ + tid];
    int r0 = tile * 2;
    for (int x = tid; x < 12 * PW_; x += 256)
        P[x] = g_ap[(b * PH_ + r0 + x / PW_) * PW_ + x % PW_];
    __syncthreads();
    for (int a = tid; a < A_; a += 256) {     // Wa @ h1 (redundant per CTA, cheap)
        const float* wr = Wa_w + (size_t)a * N_;
        float s = 0.f;
        for (int n = 0; n < N_; n += 4) {
            float4 w4 = *(const float4*)(wr + n);
            s += w4.x * h1s[n] + w4.y * h1s[n + 1] + w4.z * h1s[n + 2] + w4.w * h1s[n + 3];
        }
        Wah[a] = s;
    }
    __syncthreads();

    int w = tid >> 5, l = tid & 31;
    int lr = w >> 2, c0 = (w & 3) * 12;      // warp -> row-in-tile, 12-col group
    const float* prowbase = P + lr * PW_ + c0;
    int posbase = tile * 96 + w * 12;
    float ep[12];
#pragma unroll
    for (int j = 0; j < 12; j++) ep[j] = 0.f;

    for (int chunk = 0; chunk < 4; ++chunk) {
        for (int x = tid; x < 121 * 128; x += 256)
            Rs[x] = g_RT[(x >> 7) * A_ + chunk * 128 + (x & 127)];
        __syncthreads();
        float acc[4][12];
#pragma unroll
        for (int i = 0; i < 4; i++)
#pragma unroll
            for (int j = 0; j < 12; j++) acc[i][j] = 0.f;
        for (int dy = 0; dy < 11; ++dy) {
            const float* prow = prowbase + dy * PW_;
            const float* rrow = Rs + dy * 11 * 128 + l;
#pragma unroll
            for (int dx = 0; dx < 11; ++dx) {
                float rv0 = rrow[dx * 128];
                float rv1 = rrow[dx * 128 + 32];
                float rv2 = rrow[dx * 128 + 64];
                float rv3 = rrow[dx * 128 + 96];
#pragma unroll
                for (int j = 0; j < 12; ++j) {
                    float pv = prow[dx + j];
                    acc[0][j] = fmaf(rv0, pv, acc[0][j]);
                    acc[1][j] = fmaf(rv1, pv, acc[1][j]);
                    acc[2][j] = fmaf(rv2, pv, acc[2][j]);
                    acc[3][j] = fmaf(rv3, pv, acc[3][j]);
                }
            }
        }
#pragma unroll
        for (int i = 0; i < 4; ++i) {
            int a = chunk * 128 + i * 32 + l;
            float vav = va_w[a];
            float wahv = Wah[a];
            const float* up = g_Uctx + ((size_t)b * HW_ + posbase) * A_ + a;
#pragma unroll
            for (int j = 0; j < 12; ++j) {
                float xv = acc[i][j] + up[(size_t)j * A_] + wahv;
                ep[j] += vav * tanh_acc(xv);
            }
        }
        __syncthreads();
    }
#pragma unroll
    for (int j = 0; j < 12; ++j) {       // reduce the 32 lanes (128 'a' channels)
        float v = ep[j];
        v += __shfl_down_sync(0xffffffffu, v, 16);
        v += __shfl_down_sync(0xffffffffu, v, 8);
        v += __shfl_down_sync(0xffffffffu, v, 4);
        v += __shfl_down_sync(0xffffffffu, v, 2);
        v += __shfl_down_sync(0xffffffffu, v, 1);
        ep[j] = v;
    }
    if (l == 0) {
        float vb = va_b[0];
        float ssum = 0.f;
#pragma unroll
        for (int j = 0; j < 12; ++j) {
            int pos = posbase + j;
            float ee = __expf(ep[j] + vb) * cmask[b * HW_ + pos];
            g_ee[b * HW_ + pos] = ee;
            ssum += ee;
        }
        atomicAdd(&g_S[b], ssum);
    }
}

// ------------- per step: fused softmax + ap + ct + GRU2 + GRU1(t+1) -------------
// grid (B,), 256 threads. h2 handed to GRU1 through shared memory.
__global__ void k_fused(const float* __restrict__ ctx,
                        const float* __restrict__ Wcz, const float* __restrict__ Wcr,
                        const float* __restrict__ Wch,
                        const float* __restrict__ Uhz2, const float* __restrict__ bz2,
                        const float* __restrict__ Uhr2, const float* __restrict__ br2,
                        const float* __restrict__ Uhh2, const float* __restrict__ bh2,
                        const float* __restrict__ Uhz, const float* __restrict__ Uhr,
                        const float* __restrict__ Uhh,
                        const float* __restrict__ mask, int t,
                        float* __restrict__ o_al, float* __restrict__ o_ap,
                        float* __restrict__ o_ct, float* __restrict__ o_h2) {
    __shared__ float als[HW_];
    __shared__ float cts[D_];
    __shared__ float h1s[N_];
    __shared__ float h2s[N_];
    __shared__ float sinv;
    int b = blockIdx.x, tid = threadIdx.x;
    if (tid == 0) sinv = __fdividef(1.f, g_S[b]);
    h1s[tid] = g_h1[b * N_ + tid];
    __syncthreads();
    if (tid == 0) g_S[b] = 0.f;         // reset denom for next step's conv
    float inv = sinv;
    // softmax + alpha_past update + outputs
    for (int x = tid; x < HW_; x += 256) {
        float av = g_ee[b * HW_ + x] * inv;
        als[x] = av;
        o_al[(size_t)(t * B_ + b) * HW_ + x] = av;
        int r = x / W_, c = x - r * W_;
        int api = (b * PH_ + r + 5) * PW_ + c + 5;
        float apn = g_ap[api] + av;
        g_ap[api] = apn;
        o_ap[(size_t)(t * B_ + b) * HW_ + x] = apn;
    }
    __syncthreads();
    // context vector ct[b][d]
    for (int d = tid; d < D_; d += 256) {
        const float* crow = ctx + ((size_t)b * D_ + d) * HW_;
        float s0 = 0.f, s1 = 0.f, s2 = 0.f, s3 = 0.f;
        for (int x = 0; x < HW_; x += 4) {
            float4 c4 = *(const float4*)(crow + x);
            s0 += c4.x * als[x];
            s1 += c4.y * als[x + 1];
            s2 += c4.z * als[x + 2];
            s3 += c4.w * als[x + 3];
        }
        float ctv = (s0 + s1) + (s2 + s3);
        cts[d] = ctv;
        o_ct[(size_t)(t * B_ + b) * D_ + d] = ctv;
    }
    __syncthreads();
    // GRU2: n = tid
    {
        int n = tid;
        const float* wz = Wcz + (size_t)n * D_;
        const float* wr = Wcr + (size_t)n * D_;
        const float* wh = Wch + (size_t)n * D_;
        float cz = 0.f, cr = 0.f, ch = 0.f;
        for (int d = 0; d < D_; d += 4) {
            float4 z4 = *(const float4*)(wz + d);
            float4 r4 = *(const float4*)(wr + d);
            float4 h4 = *(const float4*)(wh + d);
            float c0 = cts[d], c1 = cts[d + 1], c2 = cts[d + 2], c3 = cts[d + 3];
            cz += z4.x * c0 + z4.y * c1 + z4.z * c2 + z4.w * c3;
            cr += r4.x * c0 + r4.y * c1 + r4.z * c2 + r4.w * c3;
            ch += h4.x * c0 + h4.y * c1 + h4.z * c2 + h4.w * c3;
        }
        const float* uz = Uhz2 + (size_t)n * N_;
        const float* ur = Uhr2 + (size_t)n * N_;
        const float* uh = Uhh2 + (size_t)n * N_;
        float az = 0.f, ar = 0.f, ah = 0.f;
        for (int m = 0; m < N_; m += 4) {
            float4 z4 = *(const float4*)(uz + m);
            float4 r4 = *(const float4*)(ur + m);
            float4 h4 = *(const float4*)(uh + m);
            float e0 = h1s[m], e1 = h1s[m + 1], e2 = h1s[m + 2], e3 = h1s[m + 3];
            az += z4.x * e0 + z4.y * e1 + z4.z * e2 + z4.w * e3;
            ar += r4.x * e0 + r4.y * e1 + r4.z * e2 + r4.w * e3;
            ah += h4.x * e0 + h4.y * e1 + h4.z * e2 + h4.w * e3;
        }
        float z2 = sigm(cz + az + bz2[n]);
        float r2 = sigm(cr + ar + br2[n]);
        float h2p = tanh_acc(ch + (ah + bh2[n]) * r2);
        float h1v = h1s[n];
        float h2 = z2 * h1v + (1.f - z2) * h2p;
        float m = mask[t * B_ + b];
        h2 = m * h2 + (1.f - m) * h1v;
        h2s[n] = h2;
        o_h2[(size_t)(t * B_ + b) * N_ + n] = h2;
    }
    __syncthreads();
    // GRU1 for step t+1 (consumes h2 from smem)
    if (t + 1 < T_) {
        int n = tid;
        const float* wz = Uhz + (size_t)n * N_;
        const float* wr = Uhr + (size_t)n * N_;
        const float* wh = Uhh + (size_t)n * N_;
        float az = 0.f, ar = 0.f, ah = 0.f;
        for (int m = 0; m < N_; m += 4) {
            float4 z4 = *(const float4*)(wz + m);
            float4 r4 = *(const float4*)(wr + m);
            float4 h4 = *(const float4*)(wh + m);
            float e0 = h2s[m], e1 = h2s[m + 1], e2 = h2s[m + 2], e3 = h2s[m + 3];
            az += z4.x * e0 + z4.y * e1 + z4.z * e2 + z4.w * e3;
            ar += r4.x * e0 + r4.y * e1 + r4.z * e2 + r4.w * e3;
            ah += h4.x * e0 + h4.y * e1 + h4.z * e2 + h4.w * e3;
        }
        int tb = (t + 1) * B_ + b;
        float z1 = sigm(az + g_sz[tb * N_ + n]);
        float r1 = sigm(ar + g_sr[tb * N_ + n]);
        float h1p = tanh_acc(ah * r1 + g_sh[tb * N_ + n]);
        float hv = h2s[n];
        float h1 = z1 * hv + (1.f - z1) * h1p;
        float m = mask[tb];
        g_h1[b * N_ + n] = m * h1 + (1.f - m) * hv;
    }
}

extern "C" void kernel_launch(void* const* d_in, const int* in_sizes, int n_in,
                              void* d_out, int out_size) {
    const float* emb   = (const float*)d_in[0];
    const float* mask  = (const float*)d_in[1];
    const float* ctx   = (const float*)d_in[2];
    const float* cmask = (const float*)d_in[3];
    const float* h0    = (const float*)d_in[4];
    const float* Ua_w  = (const float*)d_in[5];
    const float* Ua_b  = (const float*)d_in[6];
    const float* Wa_w  = (const float*)d_in[7];
    const float* Q_w   = (const float*)d_in[8];
    const float* Uf_w  = (const float*)d_in[9];
    const float* Uf_b  = (const float*)d_in[10];
    const float* va_w  = (const float*)d_in[11];
    const float* va_b  = (const float*)d_in[12];
    const float* Wyz_w = (const float*)d_in[13];
    const float* Wyz_b = (const float*)d_in[14];
    const float* Wyr_w = (const float*)d_in[15];
    const float* Wyr_b = (const float*)d_in[16];
    const float* Wyh_w = (const float*)d_in[17];
    const float* Wyh_b = (const float*)d_in[18];
    const float* Uhz_w = (const float*)d_in[19];
    const float* Uhr_w = (const float*)d_in[20];
    const float* Uhh_w = (const float*)d_in[21];
    const float* Wcz_w = (const float*)d_in[22];
    const float* Wcr_w = (const float*)d_in[23];
    const float* Wch_w = (const float*)d_in[24];
    const float* Uhz2_w = (const float*)d_in[25];
    const float* Uhz2_b = (const float*)d_in[26];
    const float* Uhr2_w = (const float*)d_in[27];
    const float* Uhr2_b = (const float*)d_in[28];
    const float* Uhh2_w = (const float*)d_in[29];
    const float* Uhh2_b = (const float*)d_in[30];

    float* out  = (float*)d_out;
    float* o_h2 = out;                                   // [T,B,N]
    float* o_ct = o_h2 + (size_t)T_ * B_ * N_;           // [T,B,D]
    float* o_al = o_ct + (size_t)T_ * B_ * D_;           // [T,B,H,W]
    float* o_ap = o_al + (size_t)T_ * B_ * HW_;          // [T,B,H,W]

    static int smem_set = 0;
    if (!smem_set) {
        cudaFuncSetAttribute(k_conv, cudaFuncAttributeMaxDynamicSharedMemorySize,
                             CONV_SMEM_BYTES);
        smem_set = 1;
    }

    // one-time precomputes
    k_pre_R<<<121, 256>>>(Uf_w, Q_w);
    k_pre_szrh<<<T_ * B_, 256>>>(emb, Wyz_w, Wyz_b, Wyr_w, Wyr_b, Wyh_w, Wyh_b);
    k_uactx<<<dim3(HW_ / 64, A_ / 64, B_), 256>>>(ctx, Ua_w, Ua_b, Uf_b);
    k_init<<<(B_ * PH_ * PW_ + 255) / 256, 256>>>(h0);
    k_gru1<<<dim3(B_, 4), 64>>>(Uhz_w, Uhr_w, Uhh_w, mask, 0);   // prologue h1(0)

    // 48 sequential steps, 2 launches each
    for (int t = 0; t < T_; ++t) {
        k_conv<<<dim3(B_, 8), 256, CONV_SMEM_BYTES>>>(Wa_w, va_w, va_b, cmask, t);
        k_fused<<<B_, 256>>>(ctx, Wcz_w, Wcr_w, Wch_w, Uhz2_w, Uhz2_b,
                             Uhr2_w, Uhr2_b, Uhh2_w, Uhh2_b,
                             Uhz_w, Uhr_w, Uhh_w, mask, t,
                             o_al, o_ap, o_ct, o_h2);
    }
    (void)in_sizes; (void)n_in; (void)out_size;
}

// round 12
// speedup vs baseline: 1.0878x; 1.0854x over previous
#include <cuda_runtime.h>
#include <math.h>

#define T_ 48
#define B_ 16
#define H_ 16
#define W_ 48
#define D_ 684
#define N_ 256
#define M_ 256
#define A_ 512
#define CQ_ 512
#define HW_ 768
#define PH_ 26
#define PW_ 58

// ------------- device scratch (no dynamic allocation allowed) -------------
__device__ float g_RT[121 * A_];            // R^T: [k][a]
__device__ float g_Uctx[B_ * HW_ * A_];     // Ua_ctx + Ua_b + Uf_b, [b][pos][a]
__device__ float g_ctxT[(size_t)B_ * HW_ * D_];  // ctx transposed: [b][x][d]
__device__ float g_WcT[3 * D_ * N_];        // Wcz/Wcr/Wch transposed: [g][d][n]
__device__ float g_U2T[3 * N_ * N_];        // Uhz2/Uhr2/Uhh2 transposed: [g][m][n]
__device__ float g_U1T[3 * N_ * N_];        // Uhz/Uhr/Uhh transposed: [g][m][n]
__device__ float g_sz[T_ * B_ * N_];
__device__ float g_sr[T_ * B_ * N_];
__device__ float g_sh[T_ * B_ * N_];
__device__ float g_h[B_ * N_];
__device__ float g_h1[B_ * N_];
__device__ float g_ap[B_ * PH_ * PW_];      // zero-padded alpha_past
__device__ float g_ee[B_ * HW_];            // exp(e)*mask
__device__ float g_S[B_];                   // softmax denominators
__device__ float g_ct[B_ * D_];

__device__ __forceinline__ float sigm(float x) {
    return __fdividef(1.f, 1.f + __expf(-x));
}
__device__ __forceinline__ float tanh_acc(float x) {
    float z = __expf(2.f * x);
    return 1.f - __fdividef(2.f, z + 1.f);
}

// ------------- precompute R^T + ALL transposes (one-time) -------------
__global__ void k_pre_R(const float* __restrict__ Uf_w, const float* __restrict__ Q_w,
                        const float* __restrict__ ctx,
                        const float* __restrict__ Wcz, const float* __restrict__ Wcr,
                        const float* __restrict__ Wch,
                        const float* __restrict__ Uhz2, const float* __restrict__ Uhr2,
                        const float* __restrict__ Uhh2,
                        const float* __restrict__ Uhz, const float* __restrict__ Uhr,
                        const float* __restrict__ Uhh) {
    __shared__ float Qs[CQ_];
    int k = blockIdx.x;  // 0..120
    int tid = threadIdx.x;
    for (int c = tid; c < CQ_; c += 256) Qs[c] = Q_w[c * 121 + k];
    __syncthreads();
    for (int a = tid; a < A_; a += 256) {
        const float* u = Uf_w + (size_t)a * CQ_;
        float s = 0.f;
        for (int c = 0; c < CQ_; c += 4) {
            float4 u4 = *(const float4*)(u + c);
            s += u4.x * Qs[c] + u4.y * Qs[c + 1] + u4.z * Qs[c + 2] + u4.w * Qs[c + 3];
        }
        g_RT[k * A_ + a] = s;
    }
    // grid-strided transposes (independent of R work)
    size_t gid = (size_t)blockIdx.x * 256 + tid;
    size_t gstride = (size_t)gridDim.x * 256;
    // ctxT[b][x][d] = ctx[b][d][x]
    for (size_t i = gid; i < (size_t)B_ * HW_ * D_; i += gstride) {
        int d = (int)(i % D_);
        size_t r = i / D_;
        int x = (int)(r % HW_);
        int b = (int)(r / HW_);
        g_ctxT[i] = ctx[((size_t)b * D_ + d) * HW_ + x];
    }
    // WcT[g][d][n] = Wc*[n][d]
    for (size_t i = gid; i < (size_t)3 * D_ * N_; i += gstride) {
        int n = (int)(i % N_);
        size_t r = i / N_;
        int d = (int)(r % D_);
        int g = (int)(r / D_);
        const float* Wsrc = (g == 0) ? Wcz : (g == 1) ? Wcr : Wch;
        g_WcT[i] = Wsrc[(size_t)n * D_ + d];
    }
    // U2T[g][m][n] = Uh*2[n][m]
    for (size_t i = gid; i < (size_t)3 * N_ * N_; i += gstride) {
        int n = (int)(i % N_);
        size_t r = i / N_;
        int m = (int)(r % N_);
        int g = (int)(r / N_);
        const float* Usrc = (g == 0) ? Uhz2 : (g == 1) ? Uhr2 : Uhh2;
        g_U2T[i] = Usrc[(size_t)n * N_ + m];
    }
    // U1T[g][m][n] = Uh*[n][m]
    for (size_t i = gid; i < (size_t)3 * N_ * N_; i += gstride) {
        int n = (int)(i % N_);
        size_t r = i / N_;
        int m = (int)(r % N_);
        int g = (int)(r / N_);
        const float* Usrc = (g == 0) ? Uhz : (g == 1) ? Uhr : Uhh;
        g_U1T[i] = Usrc[(size_t)n * N_ + m];
    }
}

// ------------- precompute sz/sr/sh = emb @ Wy*.T + b -------------
__global__ void k_pre_szrh(const float* __restrict__ emb,
                           const float* __restrict__ Wyz, const float* __restrict__ bz,
                           const float* __restrict__ Wyr, const float* __restrict__ br,
                           const float* __restrict__ Wyh, const float* __restrict__ bh) {
    __shared__ float es[M_];
    int tb = blockIdx.x;
    es[threadIdx.x] = emb[(size_t)tb * M_ + threadIdx.x];
    __syncthreads();
    int n = threadIdx.x;
    const float* wz = Wyz + (size_t)n * M_;
    const float* wr = Wyr + (size_t)n * M_;
    const float* wh = Wyh + (size_t)n * M_;
    float az = 0.f, ar = 0.f, ah = 0.f;
    for (int m = 0; m < M_; m += 4) {
        float4 z4 = *(const float4*)(wz + m);
        float4 r4 = *(const float4*)(wr + m);
        float4 h4 = *(const float4*)(wh + m);
        float e0 = es[m], e1 = es[m + 1], e2 = es[m + 2], e3 = es[m + 3];
        az += z4.x * e0 + z4.y * e1 + z4.z * e2 + z4.w * e3;
        ar += r4.x * e0 + r4.y * e1 + r4.z * e2 + r4.w * e3;
        ah += h4.x * e0 + h4.y * e1 + h4.z * e2 + h4.w * e3;
    }
    g_sz[tb * N_ + n] = az + bz[n];
    g_sr[tb * N_ + n] = ar + br[n];
    g_sh[tb * N_ + n] = ah + bh[n];
}

// ------------- precompute Uctx[b][pos][a] = ctx . Ua_w + Ua_b + Uf_b -------------
__global__ void k_uactx(const float* __restrict__ ctx, const float* __restrict__ Ua_w,
                        const float* __restrict__ Ua_b, const float* __restrict__ Uf_b) {
    __shared__ float As[16][64];   // [dd][pos]
    __shared__ float Bs[16][68];   // [dd][a], padded
    int b = blockIdx.z;
    int p0 = blockIdx.x * 64;
    int a0 = blockIdx.y * 64;
    int tid = threadIdx.x;
    int ty = tid >> 4, tx = tid & 15;
    float acc[4][4];
#pragma unroll
    for (int i = 0; i < 4; i++)
#pragma unroll
        for (int j = 0; j < 4; j++) acc[i][j] = 0.f;

    int dda = tid >> 4;
    int pp4 = (tid & 15) * 4;
    int aab = tid >> 2;
    int dd4 = (tid & 3) * 4;

    for (int d0 = 0; d0 < D_; d0 += 16) {
        float4 av = make_float4(0.f, 0.f, 0.f, 0.f);
        if (d0 + dda < D_)
            av = *(const float4*)(ctx + ((size_t)b * D_ + d0 + dda) * HW_ + p0 + pp4);
        *(float4*)&As[dda][pp4] = av;
        float4 bv = make_float4(0.f, 0.f, 0.f, 0.f);
        if (d0 + dd4 < D_)
            bv = *(const float4*)(Ua_w + (size_t)(a0 + aab) * D_ + d0 + dd4);
        Bs[dd4][aab] = bv.x;
        Bs[dd4 + 1][aab] = bv.y;
        Bs[dd4 + 2][aab] = bv.z;
        Bs[dd4 + 3][aab] = bv.w;
        __syncthreads();
#pragma unroll
        for (int dd = 0; dd < 16; ++dd) {
            float4 af = *(const float4*)&As[dd][ty * 4];
            float4 bf = *(const float4*)&Bs[dd][tx * 4];
            acc[0][0] += af.x * bf.x; acc[0][1] += af.x * bf.y; acc[0][2] += af.x * bf.z; acc[0][3] += af.x * bf.w;
            acc[1][0] += af.y * bf.x; acc[1][1] += af.y * bf.y; acc[1][2] += af.y * bf.z; acc[1][3] += af.y * bf.w;
            acc[2][0] += af.z * bf.x; acc[2][1] += af.z * bf.y; acc[2][2] += af.z * bf.z; acc[2][3] += af.z * bf.w;
            acc[3][0] += af.w * bf.x; acc[3][1] += af.w * bf.y; acc[3][2] += af.w * bf.z; acc[3][3] += af.w * bf.w;
        }
        __syncthreads();
    }
#pragma unroll
    for (int i = 0; i < 4; i++) {
        int pos = p0 + ty * 4 + i;
#pragma unroll
        for (int j = 0; j < 4; j++) {
            int a = a0 + tx * 4 + j;
            g_Uctx[((size_t)b * HW_ + pos) * A_ + a] = acc[i][j] + Ua_b[a] + Uf_b[a];
        }
    }
}

// ------------- prologue: zero ap/S + GRU1(t=0) from h0 (row-major weights) -----
__global__ void k_init_gru1(const float* __restrict__ h0,
                            const float* __restrict__ Uhz, const float* __restrict__ Uhr,
                            const float* __restrict__ Uhh, const float* __restrict__ mask) {
    __shared__ float hs[N_];
    int b = blockIdx.x, s = blockIdx.y, tid = threadIdx.x;
    int gtid = ((b * 4 + s) * 64) + tid;
    for (int i = gtid; i < B_ * PH_ * PW_; i += 4096) g_ap[i] = 0.f;
    if (gtid < B_) g_S[gtid] = 0.f;
    for (int x = tid; x < N_; x += 64) hs[x] = h0[b * N_ + x];
    __syncthreads();
    int n = s * 64 + tid;
    const float* wz = Uhz + (size_t)n * N_;
    const float* wr = Uhr + (size_t)n * N_;
    const float* wh = Uhh + (size_t)n * N_;
    float az = 0.f, ar = 0.f, ah = 0.f;
    for (int m = 0; m < N_; m += 4) {
        float4 z4 = *(const float4*)(wz + m);
        float4 r4 = *(const float4*)(wr + m);
        float4 h4 = *(const float4*)(wh + m);
        float e0 = hs[m], e1 = hs[m + 1], e2 = hs[m + 2], e3 = hs[m + 3];
        az += z4.x * e0 + z4.y * e1 + z4.z * e2 + z4.w * e3;
        ar += r4.x * e0 + r4.y * e1 + r4.z * e2 + r4.w * e3;
        ah += h4.x * e0 + h4.y * e1 + h4.z * e2 + h4.w * e3;
    }
    int tb = b;  // t = 0
    float z1 = sigm(az + g_sz[tb * N_ + n]);
    float r1 = sigm(ar + g_sr[tb * N_ + n]);
    float h1p = tanh_acc(ah * r1 + g_sh[tb * N_ + n]);
    float hv = hs[n];
    float h1 = z1 * hv + (1.f - z1) * h1p;
    float m = mask[tb];
    g_h1[b * N_ + n] = m * h1 + (1.f - m) * hv;
}

// ------------- per step: coverage-conv + attention energies (scalar FFMA) -----
#define CONV_SMEM_BYTES ((121 * 128 + 12 * PW_ + A_ + N_) * 4)
__global__ __launch_bounds__(256, 1) void k_conv(const float* __restrict__ Wa_w,
                                                 const float* __restrict__ va_w,
                                                 const float* __restrict__ va_b,
                                                 const float* __restrict__ cmask, int t) {
    extern __shared__ float sm[];
    float* Rs = sm;                      // [121][128]
    float* P = Rs + 121 * 128;           // [12][PW_]
    float* Wah = P + 12 * PW_;           // [512]
    float* h1s = Wah + A_;               // [256]
    int b = blockIdx.x, tile = blockIdx.y;
    int tid = threadIdx.x;
    h1s[tid] = g_h1[b * N_ + tid];
    int r0 = tile * 2;
    for (int x = tid; x < 12 * PW_; x += 256)
        P[x] = g_ap[(b * PH_ + r0 + x / PW_) * PW_ + x % PW_];
    __syncthreads();
    for (int a = tid; a < A_; a += 256) {     // Wa @ h1 (redundant per CTA, cheap)
        const float* wr = Wa_w + (size_t)a * N_;
        float s = 0.f;
        for (int n = 0; n < N_; n += 4) {
            float4 w4 = *(const float4*)(wr + n);
            s += w4.x * h1s[n] + w4.y * h1s[n + 1] + w4.z * h1s[n + 2] + w4.w * h1s[n + 3];
        }
        Wah[a] = s;
    }
    __syncthreads();

    int w = tid >> 5, l = tid & 31;
    int lr = w >> 2, c0 = (w & 3) * 12;      // warp -> row-in-tile, 12-col group
    const float* prowbase = P + lr * PW_ + c0;
    int posbase = tile * 96 + w * 12;
    float ep[12];
#pragma unroll
    for (int j = 0; j < 12; j++) ep[j] = 0.f;

    for (int chunk = 0; chunk < 4; ++chunk) {
        for (int x = tid; x < 121 * 128; x += 256)
            Rs[x] = g_RT[(x >> 7) * A_ + chunk * 128 + (x & 127)];
        __syncthreads();
        float acc[4][12];
#pragma unroll
        for (int i = 0; i < 4; i++)
#pragma unroll
            for (int j = 0; j < 12; j++) acc[i][j] = 0.f;
        for (int dy = 0; dy < 11; ++dy) {
            const float* prow = prowbase + dy * PW_;
            const float* rrow = Rs + dy * 11 * 128 + l;
#pragma unroll
            for (int dx = 0; dx < 11; ++dx) {
                float rv0 = rrow[dx * 128];
                float rv1 = rrow[dx * 128 + 32];
                float rv2 = rrow[dx * 128 + 64];
                float rv3 = rrow[dx * 128 + 96];
#pragma unroll
                for (int j = 0; j < 12; ++j) {
                    float pv = prow[dx + j];
                    acc[0][j] = fmaf(rv0, pv, acc[0][j]);
                    acc[1][j] = fmaf(rv1, pv, acc[1][j]);
                    acc[2][j] = fmaf(rv2, pv, acc[2][j]);
                    acc[3][j] = fmaf(rv3, pv, acc[3][j]);
                }
            }
        }
#pragma unroll
        for (int i = 0; i < 4; ++i) {
            int a = chunk * 128 + i * 32 + l;
            float vav = va_w[a];
            float wahv = Wah[a];
            const float* up = g_Uctx + ((size_t)b * HW_ + posbase) * A_ + a;
#pragma unroll
            for (int j = 0; j < 12; ++j) {
                float xv = acc[i][j] + up[(size_t)j * A_] + wahv;
                ep[j] += vav * tanh_acc(xv);
            }
        }
        __syncthreads();
    }
#pragma unroll
    for (int j = 0; j < 12; ++j) {
        float v = ep[j];
        v += __shfl_down_sync(0xffffffffu, v, 16);
        v += __shfl_down_sync(0xffffffffu, v, 8);
        v += __shfl_down_sync(0xffffffffu, v, 4);
        v += __shfl_down_sync(0xffffffffu, v, 2);
        v += __shfl_down_sync(0xffffffffu, v, 1);
        ep[j] = v;
    }
    if (l == 0) {
        float vb = va_b[0];
        float ssum = 0.f;
#pragma unroll
        for (int j = 0; j < 12; ++j) {
            int pos = posbase + j;
            float ee = __expf(ep[j] + vb) * cmask[b * HW_ + pos];
            g_ee[b * HW_ + pos] = ee;
            ssum += ee;
        }
        atomicAdd(&g_S[b], ssum);
    }
}

// ------------- per step: softmax + ap update + ct (coalesced via ctxT) --------
// grid (B, 4), 192 threads. CTA s handles d in [s*171, (s+1)*171).
__global__ void k_attn(int t, float* __restrict__ o_al, float* __restrict__ o_ap,
                       float* __restrict__ o_ct) {
    __shared__ float als[HW_];
    int b = blockIdx.x, s = blockIdx.y, tid = threadIdx.x;
    float inv = __fdividef(1.f, g_S[b]);
    for (int x = tid; x < HW_; x += 192) als[x] = g_ee[b * HW_ + x] * inv;
    __syncthreads();
    if (s == 0) {
        for (int x = tid; x < HW_; x += 192) {
            float av = als[x];
            o_al[(size_t)(t * B_ + b) * HW_ + x] = av;
            int r = x / W_, c = x - r * W_;
            int api = (b * PH_ + r + 5) * PW_ + c + 5;
            float apn = g_ap[api] + av;
            g_ap[api] = apn;
            o_ap[(size_t)(t * B_ + b) * HW_ + x] = apn;
        }
    }
    if (tid < 171) {
        int d = s * 171 + tid;
        const float* cT = g_ctxT + (size_t)b * HW_ * D_ + d;
        float a0 = 0.f, a1 = 0.f, a2 = 0.f, a3 = 0.f;
        for (int x = 0; x < HW_; x += 4) {
            a0 += cT[(size_t)x * D_] * als[x];
            a1 += cT[(size_t)(x + 1) * D_] * als[x + 1];
            a2 += cT[(size_t)(x + 2) * D_] * als[x + 2];
            a3 += cT[(size_t)(x + 3) * D_] * als[x + 3];
        }
        float v = (a0 + a1) + (a2 + a3);
        g_ct[b * D_ + d] = v;
        o_ct[(size_t)(t * B_ + b) * D_ + d] = v;
    }
}

// ------------- per step: GRU2 (coalesced transposed weights) -------------
__global__ void k_gru2(const float* __restrict__ bz2, const float* __restrict__ br2,
                       const float* __restrict__ bh2, const float* __restrict__ mask,
                       int t, float* __restrict__ o_h2) {
    __shared__ float cts[D_];
    __shared__ float h1s[N_];
    int b = blockIdx.x, s = blockIdx.y, tid = threadIdx.x;
    for (int x = tid; x < D_; x += 64) cts[x] = g_ct[b * D_ + x];
    for (int x = tid; x < N_; x += 64) h1s[x] = g_h1[b * N_ + x];
    __syncthreads();
    int n = s * 64 + tid;
    float cz = 0.f, cr = 0.f, ch = 0.f;
#pragma unroll 4
    for (int d = 0; d < D_; ++d) {
        float cv = cts[d];
        cz = fmaf(g_WcT[(0 * D_ + d) * N_ + n], cv, cz);
        cr = fmaf(g_WcT[(1 * D_ + d) * N_ + n], cv, cr);
        ch = fmaf(g_WcT[(2 * D_ + d) * N_ + n], cv, ch);
    }
    float az = 0.f, ar = 0.f, ah = 0.f;
#pragma unroll 4
    for (int m = 0; m < N_; ++m) {
        float hv = h1s[m];
        az = fmaf(g_U2T[(0 * N_ + m) * N_ + n], hv, az);
        ar = fmaf(g_U2T[(1 * N_ + m) * N_ + n], hv, ar);
        ah = fmaf(g_U2T[(2 * N_ + m) * N_ + n], hv, ah);
    }
    float z2 = sigm(cz + az + bz2[n]);
    float r2 = sigm(cr + ar + br2[n]);
    float h2p = tanh_acc(ch + (ah + bh2[n]) * r2);
    float h1v = h1s[n];
    float h2 = z2 * h1v + (1.f - z2) * h2p;
    float m = mask[t * B_ + b];
    h2 = m * h2 + (1.f - m) * h1v;
    g_h[b * N_ + n] = h2;
    o_h2[(size_t)(t * B_ + b) * N_ + n] = h2;
}

// ------------- per step: GRU1 for step t (coalesced transposed weights) -------
__global__ void k_gru1T(const float* __restrict__ mask, int t) {
    __shared__ float hs[N_];
    int b = blockIdx.x, s = blockIdx.y, tid = threadIdx.x;
    for (int x = tid; x < N_; x += 64) hs[x] = g_h[b * N_ + x];
    if (s == 0 && tid == 0) g_S[b] = 0.f;   // reset denom before next conv
    __syncthreads();
    int n = s * 64 + tid;
    float az = 0.f, ar = 0.f, ah = 0.f;
#pragma unroll 4
    for (int m = 0; m < N_; ++m) {
        float hv = hs[m];
        az = fmaf(g_U1T[(0 * N_ + m) * N_ + n], hv, az);
        ar = fmaf(g_U1T[(1 * N_ + m) * N_ + n], hv, ar);
        ah = fmaf(g_U1T[(2 * N_ + m) * N_ + n], hv, ah);
    }
    int tb = t * B_ + b;
    float z1 = sigm(az + g_sz[tb * N_ + n]);
    float r1 = sigm(ar + g_sr[tb * N_ + n]);
    float h1p = tanh_acc(ah * r1 + g_sh[tb * N_ + n]);
    float hv = hs[n];
    float h1 = z1 * hv + (1.f - z1) * h1p;
    float m = mask[tb];
    g_h1[b * N_ + n] = m * h1 + (1.f - m) * hv;
}

extern "C" void kernel_launch(void* const* d_in, const int* in_sizes, int n_in,
                              void* d_out, int out_size) {
    const float* emb   = (const float*)d_in[0];
    const float* mask  = (const float*)d_in[1];
    const float* ctx   = (const float*)d_in[2];
    const float* cmask = (const float*)d_in[3];
    const float* h0    = (const float*)d_in[4];
    const float* Ua_w  = (const float*)d_in[5];
    const float* Ua_b  = (const float*)d_in[6];
    const float* Wa_w  = (const float*)d_in[7];
    const float* Q_w   = (const float*)d_in[8];
    const float* Uf_w  = (const float*)d_in[9];
    const float* Uf_b  = (const float*)d_in[10];
    const float* va_w  = (const float*)d_in[11];
    const float* va_b  = (const float*)d_in[12];
    const float* Wyz_w = (const float*)d_in[13];
    const float* Wyz_b = (const float*)d_in[14];
    const float* Wyr_w = (const float*)d_in[15];
    const float* Wyr_b = (const float*)d_in[16];
    const float* Wyh_w = (const float*)d_in[17];
    const float* Wyh_b = (const float*)d_in[18];
    const float* Uhz_w = (const float*)d_in[19];
    const float* Uhr_w = (const float*)d_in[20];
    const float* Uhh_w = (const float*)d_in[21];
    const float* Wcz_w = (const float*)d_in[22];
    const float* Wcr_w = (const float*)d_in[23];
    const float* Wch_w = (const float*)d_in[24];
    const float* Uhz2_w = (const float*)d_in[25];
    const float* Uhz2_b = (const float*)d_in[26];
    const float* Uhr2_w = (const float*)d_in[27];
    const float* Uhr2_b = (const float*)d_in[28];
    const float* Uhh2_w = (const float*)d_in[29];
    const float* Uhh2_b = (const float*)d_in[30];

    float* out  = (float*)d_out;
    float* o_h2 = out;                                   // [T,B,N]
    float* o_ct = o_h2 + (size_t)T_ * B_ * N_;           // [T,B,D]
    float* o_al = o_ct + (size_t)T_ * B_ * D_;           // [T,B,H,W]
    float* o_ap = o_al + (size_t)T_ * B_ * HW_;          // [T,B,H,W]

    static int smem_set = 0;
    if (!smem_set) {
        cudaFuncSetAttribute(k_conv, cudaFuncAttributeMaxDynamicSharedMemorySize,
                             CONV_SMEM_BYTES);
        smem_set = 1;
    }

    // one-time precomputes (launches 1-4) — k_conv is launch #5 for ncu -s 5
    k_pre_R<<<121, 256>>>(Uf_w, Q_w, ctx, Wcz_w, Wcr_w, Wch_w,
                          Uhz2_w, Uhr2_w, Uhh2_w, Uhz_w, Uhr_w, Uhh_w);
    k_pre_szrh<<<T_ * B_, 256>>>(emb, Wyz_w, Wyz_b, Wyr_w, Wyr_b, Wyh_w, Wyh_b);
    k_uactx<<<dim3(HW_ / 64, A_ / 64, B_), 256>>>(ctx, Ua_w, Ua_b, Uf_b);
    k_init_gru1<<<dim3(B_, 4), 64>>>(h0, Uhz_w, Uhr_w, Uhh_w, mask);

    // 48 sequential steps
    for (int t = 0; t < T_; ++t) {
        k_conv<<<dim3(B_, 8), 256, CONV_SMEM_BYTES>>>(Wa_w, va_w, va_b, cmask, t);
        k_attn<<<dim3(B_, 4), 192>>>(t, o_al, o_ap, o_ct);
        k_gru2<<<dim3(B_, 4), 64>>>(Uhz2_b, Uhr2_b, Uhh2_b, mask, t, o_h2);
        if (t + 1 < T_)
            k_gru1T<<<dim3(B_, 4), 64>>>(mask, t + 1);
    }
    (void)in_sizes; (void)n_in; (void)out_size;
}

// round 13
// speedup vs baseline: 2.3446x; 2.1553x over previous
#include <cuda_runtime.h>
#include <math.h>

#define T_ 48
#define B_ 16
#define H_ 16
#define W_ 48
#define D_ 684
#define N_ 256
#define M_ 256
#define A_ 512
#define CQ_ 512
#define HW_ 768
#define PH_ 26
#define PW_ 58
#define NCTA 128

// ------------- device scratch -------------
__device__ float g_RT[121 * A_];            // R^T: [k][a]
__device__ float g_Uctx[B_ * HW_ * A_];     // Ua_ctx + Ua_b + Uf_b, [b][pos][a]
__device__ float g_WcT[3 * D_ * N_];        // [g][d][n]
__device__ float g_U2T[3 * N_ * N_];        // [g][m][n]
__device__ float g_U1T[3 * N_ * N_];        // [g][m][n]
__device__ float g_sz[T_ * B_ * N_];
__device__ float g_sr[T_ * B_ * N_];
__device__ float g_sh[T_ * B_ * N_];
__device__ float g_h[B_ * N_];
__device__ float g_h1[B_ * N_];
__device__ float g_ap[B_ * PH_ * PW_];
__device__ float g_ee[B_ * HW_];
__device__ float g_S[B_];
__device__ float g_ct[B_ * D_];
__device__ unsigned int g_bar;
__device__ unsigned int g_gen;

__device__ __forceinline__ float sigm(float x) {
    return __fdividef(1.f, 1.f + __expf(-x));
}
__device__ __forceinline__ float tanh_acc(float x) {
    float z = __expf(2.f * x);
    return 1.f - __fdividef(2.f, z + 1.f);
}

// sense-free generation barrier; all 128 CTAs resident -> spin is safe
__device__ __forceinline__ void grid_barrier(int tid, unsigned int& tgt) {
    __syncthreads();
    if (tid == 0) {
        __threadfence();
        unsigned int a = atomicAdd(&g_bar, 1u);
        if (a == NCTA - 1) {
            atomicExch(&g_bar, 0u);
            __threadfence();
            atomicAdd(&g_gen, 1u);
        } else {
            while ((int)(atomicAdd(&g_gen, 0u) - tgt) < 0) __nanosleep(32);
        }
    }
    __syncthreads();
    tgt++;
}

// ------------- one-time: R^T + weight transposes -------------
__global__ void k_pre_R(const float* __restrict__ Uf_w, const float* __restrict__ Q_w,
                        const float* __restrict__ Wcz, const float* __restrict__ Wcr,
                        const float* __restrict__ Wch,
                        const float* __restrict__ Uhz2, const float* __restrict__ Uhr2,
                        const float* __restrict__ Uhh2,
                        const float* __restrict__ Uhz, const float* __restrict__ Uhr,
                        const float* __restrict__ Uhh) {
    __shared__ float Qs[CQ_];
    int k = blockIdx.x;
    int tid = threadIdx.x;
    for (int c = tid; c < CQ_; c += 256) Qs[c] = Q_w[c * 121 + k];
    __syncthreads();
    for (int a = tid; a < A_; a += 256) {
        const float* u = Uf_w + (size_t)a * CQ_;
        float s = 0.f;
        for (int c = 0; c < CQ_; c += 4) {
            float4 u4 = *(const float4*)(u + c);
            s += u4.x * Qs[c] + u4.y * Qs[c + 1] + u4.z * Qs[c + 2] + u4.w * Qs[c + 3];
        }
        g_RT[k * A_ + a] = s;
    }
    size_t gid = (size_t)blockIdx.x * 256 + tid;
    size_t gstride = (size_t)gridDim.x * 256;
    for (size_t i = gid; i < (size_t)3 * D_ * N_; i += gstride) {
        int n = (int)(i % N_);
        size_t r = i / N_;
        int d = (int)(r % D_);
        int g = (int)(r / D_);
        const float* Wsrc = (g == 0) ? Wcz : (g == 1) ? Wcr : Wch;
        g_WcT[i] = Wsrc[(size_t)n * D_ + d];
    }
    for (size_t i = gid; i < (size_t)3 * N_ * N_; i += gstride) {
        int n = (int)(i % N_);
        size_t r = i / N_;
        int m = (int)(r % N_);
        int g = (int)(r / N_);
        const float* U2 = (g == 0) ? Uhz2 : (g == 1) ? Uhr2 : Uhh2;
        g_U2T[i] = U2[(size_t)n * N_ + m];
        const float* U1 = (g == 0) ? Uhz : (g == 1) ? Uhr : Uhh;
        g_U1T[i] = U1[(size_t)n * N_ + m];
    }
}

// ------------- one-time: sz/sr/sh -------------
__global__ void k_pre_szrh(const float* __restrict__ emb,
                           const float* __restrict__ Wyz, const float* __restrict__ bz,
                           const float* __restrict__ Wyr, const float* __restrict__ br,
                           const float* __restrict__ Wyh, const float* __restrict__ bh) {
    __shared__ float es[M_];
    int tb = blockIdx.x;
    es[threadIdx.x] = emb[(size_t)tb * M_ + threadIdx.x];
    __syncthreads();
    int n = threadIdx.x;
    const float* wz = Wyz + (size_t)n * M_;
    const float* wr = Wyr + (size_t)n * M_;
    const float* wh = Wyh + (size_t)n * M_;
    float az = 0.f, ar = 0.f, ah = 0.f;
    for (int m = 0; m < M_; m += 4) {
        float4 z4 = *(const float4*)(wz + m);
        float4 r4 = *(const float4*)(wr + m);
        float4 h4 = *(const float4*)(wh + m);
        float e0 = es[m], e1 = es[m + 1], e2 = es[m + 2], e3 = es[m + 3];
        az += z4.x * e0 + z4.y * e1 + z4.z * e2 + z4.w * e3;
        ar += r4.x * e0 + r4.y * e1 + r4.z * e2 + r4.w * e3;
        ah += h4.x * e0 + h4.y * e1 + h4.z * e2 + h4.w * e3;
    }
    g_sz[tb * N_ + n] = az + bz[n];
    g_sr[tb * N_ + n] = ar + br[n];
    g_sh[tb * N_ + n] = ah + bh[n];
}

// ------------- one-time: Uctx -------------
__global__ void k_uactx(const float* __restrict__ ctx, const float* __restrict__ Ua_w,
                        const float* __restrict__ Ua_b, const float* __restrict__ Uf_b) {
    __shared__ float As[16][64];
    __shared__ float Bs[16][68];
    int b = blockIdx.z;
    int p0 = blockIdx.x * 64;
    int a0 = blockIdx.y * 64;
    int tid = threadIdx.x;
    int ty = tid >> 4, tx = tid & 15;
    float acc[4][4];
#pragma unroll
    for (int i = 0; i < 4; i++)
#pragma unroll
        for (int j = 0; j < 4; j++) acc[i][j] = 0.f;
    int dda = tid >> 4;
    int pp4 = (tid & 15) * 4;
    int aab = tid >> 2;
    int dd4 = (tid & 3) * 4;
    for (int d0 = 0; d0 < D_; d0 += 16) {
        float4 av = make_float4(0.f, 0.f, 0.f, 0.f);
        if (d0 + dda < D_)
            av = *(const float4*)(ctx + ((size_t)b * D_ + d0 + dda) * HW_ + p0 + pp4);
        *(float4*)&As[dda][pp4] = av;
        float4 bv = make_float4(0.f, 0.f, 0.f, 0.f);
        if (d0 + dd4 < D_)
            bv = *(const float4*)(Ua_w + (size_t)(a0 + aab) * D_ + d0 + dd4);
        Bs[dd4][aab] = bv.x;
        Bs[dd4 + 1][aab] = bv.y;
        Bs[dd4 + 2][aab] = bv.z;
        Bs[dd4 + 3][aab] = bv.w;
        __syncthreads();
#pragma unroll
        for (int dd = 0; dd < 16; ++dd) {
            float4 af = *(const float4*)&As[dd][ty * 4];
            float4 bf = *(const float4*)&Bs[dd][tx * 4];
            acc[0][0] += af.x * bf.x; acc[0][1] += af.x * bf.y; acc[0][2] += af.x * bf.z; acc[0][3] += af.x * bf.w;
            acc[1][0] += af.y * bf.x; acc[1][1] += af.y * bf.y; acc[1][2] += af.y * bf.z; acc[1][3] += af.y * bf.w;
            acc[2][0] += af.z * bf.x; acc[2][1] += af.z * bf.y; acc[2][2] += af.z * bf.z; acc[2][3] += af.z * bf.w;
            acc[3][0] += af.w * bf.x; acc[3][1] += af.w * bf.y; acc[3][2] += af.w * bf.z; acc[3][3] += af.w * bf.w;
        }
        __syncthreads();
    }
#pragma unroll
    for (int i = 0; i < 4; i++) {
        int pos = p0 + ty * 4 + i;
#pragma unroll
        for (int j = 0; j < 4; j++) {
            int a = a0 + tx * 4 + j;
            g_Uctx[((size_t)b * HW_ + pos) * A_ + a] = acc[i][j] + Ua_b[a] + Uf_b[a];
        }
    }
}

// ------------- one-time init -------------
__global__ void k_init0(const float* __restrict__ h0) {
    int i = blockIdx.x * 256 + threadIdx.x;
    if (i < B_ * PH_ * PW_) g_ap[i] = 0.f;
    if (i < B_ * N_) g_h[i] = h0[i];
    if (i < B_) g_S[i] = 0.f;
    if (i == 0) { g_bar = 0u; g_gen = 0u; }
}

// ------------- THE persistent kernel: all 48 steps -------------
#define CONV_SMEM_FLOATS (121 * 128 + 12 * PW_ + A_ + N_)
#define PERSIST_SMEM_BYTES (CONV_SMEM_FLOATS * 4)

__global__ __launch_bounds__(256, 1) void k_persist(
    const float* __restrict__ ctx, const float* __restrict__ Wa_w,
    const float* __restrict__ va_w, const float* __restrict__ va_b,
    const float* __restrict__ cmask, const float* __restrict__ mask,
    const float* __restrict__ bz2, const float* __restrict__ br2,
    const float* __restrict__ bh2,
    float* __restrict__ o_al, float* __restrict__ o_ap,
    float* __restrict__ o_ct, float* __restrict__ o_h2)
{
    extern __shared__ float sm[];
    const int tid = threadIdx.x;
    const int b = blockIdx.x >> 3;
    const int tile = blockIdx.x & 7;
    unsigned int tgt = 1u;

    for (int t = 0; t < T_; ++t) {
        // ===== phase D: GRU1 -> g_h1 (also reset g_S) =====
        {
            float* hs = sm;                 // 256
            float* red = sm + 256;          // 3072
            float* gsum = red + 3072;       // 96
            hs[tid] = __ldcg(&g_h[b * N_ + tid]);
            if (tile == 0 && tid == 0) g_S[b] = 0.f;
            __syncthreads();
            int nl4 = (tid & 7) * 4;
            int n0 = tile * 32 + nl4;
            int slice = tid >> 3;
            float4 az = make_float4(0.f, 0.f, 0.f, 0.f), ar = az, ah = az;
            int ms = slice * 8;
#pragma unroll
            for (int m = ms; m < ms + 8; ++m) {
                float hv = hs[m];
                float4 uz = *(const float4*)&g_U1T[(size_t)(0 * N_ + m) * N_ + n0];
                float4 ur = *(const float4*)&g_U1T[(size_t)(1 * N_ + m) * N_ + n0];
                float4 uh = *(const float4*)&g_U1T[(size_t)(2 * N_ + m) * N_ + n0];
                az.x += uz.x * hv; az.y += uz.y * hv; az.z += uz.z * hv; az.w += uz.w * hv;
                ar.x += ur.x * hv; ar.y += ur.y * hv; ar.z += ur.z * hv; ar.w += ur.w * hv;
                ah.x += uh.x * hv; ah.y += uh.y * hv; ah.z += uh.z * hv; ah.w += uh.w * hv;
            }
            *(float4*)&red[(slice * 3 + 0) * 32 + nl4] = az;
            *(float4*)&red[(slice * 3 + 1) * 32 + nl4] = ar;
            *(float4*)&red[(slice * 3 + 2) * 32 + nl4] = ah;
            __syncthreads();
            if (tid < 96) {
                int comp = tid >> 5, n_l = tid & 31;
                float s = 0.f;
#pragma unroll
                for (int s2 = 0; s2 < 32; ++s2) s += red[(s2 * 3 + comp) * 32 + n_l];
                gsum[comp * 32 + n_l] = s;
            }
            __syncthreads();
            if (tid < 32) {
                int n = tile * 32 + tid;
                int tb = t * B_ + b;
                float z1 = sigm(gsum[tid] + g_sz[tb * N_ + n]);
                float r1 = sigm(gsum[32 + tid] + g_sr[tb * N_ + n]);
                float h1p = tanh_acc(gsum[64 + tid] * r1 + g_sh[tb * N_ + n]);
                float hv = hs[n];
                float h1 = z1 * hv + (1.f - z1) * h1p;
                float m = mask[tb];
                g_h1[b * N_ + n] = m * h1 + (1.f - m) * hv;
            }
        }
        grid_barrier(tid, tgt);

        // ===== phase A: coverage conv + energies -> g_ee, g_S =====
        {
            float* Rs = sm;                    // 15488
            float* P = Rs + 121 * 128;         // 696
            float* Wah = P + 12 * PW_;         // 512
            float* h1s = Wah + A_;             // 256
            h1s[tid] = __ldcg(&g_h1[b * N_ + tid]);
            int r0 = tile * 2;
            for (int x = tid; x < 12 * PW_; x += 256)
                P[x] = __ldcg(&g_ap[(b * PH_ + r0 + x / PW_) * PW_ + x % PW_]);
            __syncthreads();
            for (int a = tid; a < A_; a += 256) {
                const float* wr = Wa_w + (size_t)a * N_;
                float s = 0.f;
                for (int n = 0; n < N_; n += 4) {
                    float4 w4 = *(const float4*)(wr + n);
                    s += w4.x * h1s[n] + w4.y * h1s[n + 1] + w4.z * h1s[n + 2] + w4.w * h1s[n + 3];
                }
                Wah[a] = s;
            }
            __syncthreads();
            int w = tid >> 5, l = tid & 31;
            int lr = w >> 2, c0 = (w & 3) * 12;
            const float* prowbase = P + lr * PW_ + c0;
            int posbase = tile * 96 + w * 12;
            float ep[12];
#pragma unroll
            for (int j = 0; j < 12; j++) ep[j] = 0.f;
            for (int chunk = 0; chunk < 4; ++chunk) {
                for (int x = tid; x < 121 * 128; x += 256)
                    Rs[x] = g_RT[(x >> 7) * A_ + chunk * 128 + (x & 127)];
                __syncthreads();
                float acc[4][12];
#pragma unroll
                for (int i = 0; i < 4; i++)
#pragma unroll
                    for (int j = 0; j < 12; j++) acc[i][j] = 0.f;
                for (int dy = 0; dy < 11; ++dy) {
                    const float* prow = prowbase + dy * PW_;
                    const float* rrow = Rs + dy * 11 * 128 + l;
#pragma unroll
                    for (int dx = 0; dx < 11; ++dx) {
                        float rv0 = rrow[dx * 128];
                        float rv1 = rrow[dx * 128 + 32];
                        float rv2 = rrow[dx * 128 + 64];
                        float rv3 = rrow[dx * 128 + 96];
#pragma unroll
                        for (int j = 0; j < 12; ++j) {
                            float pv = prow[dx + j];
                            acc[0][j] = fmaf(rv0, pv, acc[0][j]);
                            acc[1][j] = fmaf(rv1, pv, acc[1][j]);
                            acc[2][j] = fmaf(rv2, pv, acc[2][j]);
                            acc[3][j] = fmaf(rv3, pv, acc[3][j]);
                        }
                    }
                }
#pragma unroll
                for (int i = 0; i < 4; ++i) {
                    int a = chunk * 128 + i * 32 + l;
                    float vav = va_w[a];
                    float wahv = Wah[a];
                    const float* up = g_Uctx + ((size_t)b * HW_ + posbase) * A_ + a;
#pragma unroll
                    for (int j = 0; j < 12; ++j) {
                        float xv = acc[i][j] + up[(size_t)j * A_] + wahv;
                        ep[j] += vav * tanh_acc(xv);
                    }
                }
                __syncthreads();
            }
#pragma unroll
            for (int j = 0; j < 12; ++j) {
                float v = ep[j];
                v += __shfl_down_sync(0xffffffffu, v, 16);
                v += __shfl_down_sync(0xffffffffu, v, 8);
                v += __shfl_down_sync(0xffffffffu, v, 4);
                v += __shfl_down_sync(0xffffffffu, v, 2);
                v += __shfl_down_sync(0xffffffffu, v, 1);
                ep[j] = v;
            }
            if (l == 0) {
                float vb = va_b[0];
                float ssum = 0.f;
#pragma unroll
                for (int j = 0; j < 12; ++j) {
                    int pos = posbase + j;
                    float ee = __expf(ep[j] + vb) * cmask[b * HW_ + pos];
                    g_ee[b * HW_ + pos] = ee;
                    ssum += ee;
                }
                atomicAdd(&g_S[b], ssum);
            }
        }
        grid_barrier(tid, tgt);

        // ===== phase B: softmax + alpha_past + ct =====
        {
            float* als = sm;                // 768
            float* red = sm + 768;          // 172
            float inv = __fdividef(1.f, __ldcg(&g_S[b]));
            for (int x = tid; x < HW_; x += 256) als[x] = __ldcg(&g_ee[b * HW_ + x]) * inv;
            __syncthreads();
            if (tile == 0) {
                for (int x = tid; x < HW_; x += 256) {
                    float av = als[x];
                    o_al[(size_t)(t * B_ + b) * HW_ + x] = av;
                    int r = x / W_, c = x - r * W_;
                    int api = (b * PH_ + r + 5) * PW_ + c + 5;
                    float apn = __ldcg(&g_ap[api]) + av;
                    g_ap[api] = apn;
                    o_ap[(size_t)(t * B_ + b) * HW_ + x] = apn;
                }
            }
            int d = tile * 86 + (tid >> 1);
            if (tid < 172 && d < D_) {
                const float* crow = ctx + ((size_t)b * D_ + d) * HW_ + (tid & 1) * 384;
                const float* alp = als + (tid & 1) * 384;
                float s0 = 0.f, s1 = 0.f, s2 = 0.f, s3 = 0.f;
                for (int x = 0; x < 384; x += 4) {
                    float4 c4 = *(const float4*)(crow + x);
                    s0 += c4.x * alp[x];
                    s1 += c4.y * alp[x + 1];
                    s2 += c4.z * alp[x + 2];
                    s3 += c4.w * alp[x + 3];
                }
                red[tid] = (s0 + s1) + (s2 + s3);
            }
            __syncthreads();
            if (tid < 86) {
                int dd = tile * 86 + tid;
                if (dd < D_) {
                    float v = red[2 * tid] + red[2 * tid + 1];
                    g_ct[b * D_ + dd] = v;
                    o_ct[(size_t)(t * B_ + b) * D_ + dd] = v;
                }
            }
        }
        grid_barrier(tid, tgt);

        // ===== phase C: GRU2 -> g_h, o_h2 =====
        {
            float* cts = sm;                   // 684
            float* h1s = sm + 684;             // 256
            float* red = sm + 684 + 256;       // 4096
            float* gsum = red + 4096;          // 128
            for (int x = tid; x < D_; x += 256) cts[x] = __ldcg(&g_ct[b * D_ + x]);
            h1s[tid] = __ldcg(&g_h1[b * N_ + tid]);
            __syncthreads();
            int nl4 = (tid & 7) * 4;
            int n0 = tile * 32 + nl4;
            int slice = tid >> 3;
            float4 az = make_float4(0.f, 0.f, 0.f, 0.f), ar = az, chd = az, ahm = az;
            int ds = slice * 22;
            int de = ds + 22; if (de > D_) de = D_;
            for (int d = ds; d < de; ++d) {
                float cv = cts[d];
                float4 wz = *(const float4*)&g_WcT[(size_t)(0 * D_ + d) * N_ + n0];
                float4 wr = *(const float4*)&g_WcT[(size_t)(1 * D_ + d) * N_ + n0];
                float4 wh = *(const float4*)&g_WcT[(size_t)(2 * D_ + d) * N_ + n0];
                az.x += wz.x * cv; az.y += wz.y * cv; az.z += wz.z * cv; az.w += wz.w * cv;
                ar.x += wr.x * cv; ar.y += wr.y * cv; ar.z += wr.z * cv; ar.w += wr.w * cv;
                chd.x += wh.x * cv; chd.y += wh.y * cv; chd.z += wh.z * cv; chd.w += wh.w * cv;
            }
            int ms = slice * 8;
#pragma unroll
            for (int m = ms; m < ms + 8; ++m) {
                float hv = h1s[m];
                float4 uz = *(const float4*)&g_U2T[(size_t)(0 * N_ + m) * N_ + n0];
                float4 ur = *(const float4*)&g_U2T[(size_t)(1 * N_ + m) * N_ + n0];
                float4 uh = *(const float4*)&g_U2T[(size_t)(2 * N_ + m) * N_ + n0];
                az.x += uz.x * hv; az.y += uz.y * hv; az.z += uz.z * hv; az.w += uz.w * hv;
                ar.x += ur.x * hv; ar.y += ur.y * hv; ar.z += ur.z * hv; ar.w += ur.w * hv;
                ahm.x += uh.x * hv; ahm.y += uh.y * hv; ahm.z += uh.z * hv; ahm.w += uh.w * hv;
            }
            *(float4*)&red[(slice * 4 + 0) * 32 + nl4] = az;
            *(float4*)&red[(slice * 4 + 1) * 32 + nl4] = ar;
            *(float4*)&red[(slice * 4 + 2) * 32 + nl4] = chd;
            *(float4*)&red[(slice * 4 + 3) * 32 + nl4] = ahm;
            __syncthreads();
            if (tid < 128) {
                int comp = tid >> 5, n_l = tid & 31;
                float s = 0.f;
#pragma unroll
                for (int s2 = 0; s2 < 32; ++s2) s += red[(s2 * 4 + comp) * 32 + n_l];
                gsum[comp * 32 + n_l] = s;
            }
            __syncthreads();
            if (tid < 32) {
                int n = tile * 32 + tid;
                float z2 = sigm(gsum[tid] + bz2[n]);
                float r2 = sigm(gsum[32 + tid] + br2[n]);
                float h2p = tanh_acc(gsum[64 + tid] + (gsum[96 + tid] + bh2[n]) * r2);
                float h1v = h1s[n];
                float h2 = z2 * h1v + (1.f - z2) * h2p;
                float m = mask[t * B_ + b];
                h2 = m * h2 + (1.f - m) * h1v;
                g_h[b * N_ + n] = h2;
                o_h2[(size_t)(t * B_ + b) * N_ + n] = h2;
            }
        }
        grid_barrier(tid, tgt);
    }
}

extern "C" void kernel_launch(void* const* d_in, const int* in_sizes, int n_in,
                              void* d_out, int out_size) {
    const float* emb   = (const float*)d_in[0];
    const float* mask  = (const float*)d_in[1];
    const float* ctx   = (const float*)d_in[2];
    const float* cmask = (const float*)d_in[3];
    const float* h0    = (const float*)d_in[4];
    const float* Ua_w  = (const float*)d_in[5];
    const float* Ua_b  = (const float*)d_in[6];
    const float* Wa_w  = (const float*)d_in[7];
    const float* Q_w   = (const float*)d_in[8];
    const float* Uf_w  = (const float*)d_in[9];
    const float* Uf_b  = (const float*)d_in[10];
    const float* va_w  = (const float*)d_in[11];
    const float* va_b  = (const float*)d_in[12];
    const float* Wyz_w = (const float*)d_in[13];
    const float* Wyz_b = (const float*)d_in[14];
    const float* Wyr_w = (const float*)d_in[15];
    const float* Wyr_b = (const float*)d_in[16];
    const float* Wyh_w = (const float*)d_in[17];
    const float* Wyh_b = (const float*)d_in[18];
    const float* Uhz_w = (const float*)d_in[19];
    const float* Uhr_w = (const float*)d_in[20];
    const float* Uhh_w = (const float*)d_in[21];
    const float* Wcz_w = (const float*)d_in[22];
    const float* Wcr_w = (const float*)d_in[23];
    const float* Wch_w = (const float*)d_in[24];
    const float* Uhz2_w = (const float*)d_in[25];
    const float* Uhz2_b = (const float*)d_in[26];
    const float* Uhr2_w = (const float*)d_in[27];
    const float* Uhr2_b = (const float*)d_in[28];
    const float* Uhh2_w = (const float*)d_in[29];
    const float* Uhh2_b = (const float*)d_in[30];

    float* out  = (float*)d_out;
    float* o_h2 = out;
    float* o_ct = o_h2 + (size_t)T_ * B_ * N_;
    float* o_al = o_ct + (size_t)T_ * B_ * D_;
    float* o_ap = o_al + (size_t)T_ * B_ * HW_;

    static int smem_set = 0;
    if (!smem_set) {
        cudaFuncSetAttribute(k_persist, cudaFuncAttributeMaxDynamicSharedMemorySize,
                             PERSIST_SMEM_BYTES);
        smem_set = 1;
    }

    k_pre_R<<<121, 256>>>(Uf_w, Q_w, Wcz_w, Wcr_w, Wch_w,
                          Uhz2_w, Uhr2_w, Uhh2_w, Uhz_w, Uhr_w, Uhh_w);
    k_pre_szrh<<<T_ * B_, 256>>>(emb, Wyz_w, Wyz_b, Wyr_w, Wyr_b, Wyh_w, Wyh_b);
    k_uactx<<<dim3(HW_ / 64, A_ / 64, B_), 256>>>(ctx, Ua_w, Ua_b, Uf_b);
    k_init0<<<(B_ * PH_ * PW_ + 255) / 256, 256>>>(h0);

    k_persist<<<NCTA, 256, PERSIST_SMEM_BYTES>>>(
        ctx, Wa_w, va_w, va_b, cmask, mask, Uhz2_b, Uhr2_b, Uhh2_b,
        o_al, o_ap, o_ct, o_h2);

    (void)in_sizes; (void)n_in; (void)out_size;
}